// round 7
// baseline (speedup 1.0000x reference)
#include <cuda_runtime.h>
#include <cuda_bf16.h>
#include <math.h>
#include <stdint.h>

// ---------------- problem constants ----------------
constexpr int R    = 4096;
constexpr int D    = 4096;
constexpr int C    = 20;
constexpr int NC   = 21;
constexpr float IMG_W = 1216.0f;
constexpr float IMG_H = 800.0f;
constexpr float SCORE_THRESH = 0.05f;
constexpr float NMS_THRESH   = 0.5f;
constexpr int TOPK = 100;
constexpr int NPAD = 48;                 // 42 logit cols padded to 48

// ---------------- mma GEMM config ----------------
constexpr int BMG = 128;                 // M per CTA
constexpr int GRB = R / BMG;             // 32 row blocks
constexpr int GKS = 8;                   // K split
constexpr int KPB = D / GKS;             // 512 K per CTA
constexpr int KC  = 64;                  // K per chunk
constexpr int NCH = KPB / KC;            // 8 chunks
constexpr int GTH = 256;                 // 8 warps

// smem layout (bytes)
constexpr int RS_A    = 144;             // 64 bf16 = 128B + 16 pad (conflict-free lds)
constexpr int RS_B    = 144;
constexpr int A_BYTES = BMG * RS_A;      // 18432
constexpr int B_BYTES = NPAD * RS_B;     // 6912
constexpr int SM_A    = 0;
constexpr int SM_B    = 2 * A_BYTES;     // 36864
constexpr int SM_TOTAL = SM_B + 2 * B_BYTES;   // 50688

// ---------------- device scratch ----------------
__device__ float g_part[GKS][R * NPAD];
__device__ float g_cls[R * NC];
__device__ float g_det[R * C];           // exp(det logit)
__device__ float g_pre[R * C];           // cls_softmax * det_exp (colsum pending)
__device__ float g_colpart[64][NC];
__device__ float4 g_bclip[R];
__device__ float g_kept[R * C];
__device__ int   g_ncand;
__device__ int   g_nmscnt;
__device__ float g_cand_val[R * C];
__device__ int   g_cand_idx[R * C];
__device__ int   g_sidx[C][R];
__device__ float g_sval[C][R];
__device__ int   g_sorder[C][R];

// ---------------- helpers ----------------
__device__ __forceinline__ uint32_t pack_bf2(float lo, float hi) {
    __nv_bfloat162 h = __floats2bfloat162_rn(lo, hi);
    return *reinterpret_cast<uint32_t*>(&h);
}
__device__ __forceinline__ uint32_t smem_u32(const void* p) {
    uint32_t a;
    asm("{ .reg .u64 t; cvta.to.shared.u64 t, %1; cvt.u32.u64 %0, t; }" : "=r"(a) : "l"(p));
    return a;
}
__device__ __forceinline__ void mma_bf16(float* c, uint32_t a0, uint32_t a1,
                                         uint32_t a2, uint32_t a3,
                                         uint32_t b0, uint32_t b1) {
    asm volatile(
        "mma.sync.aligned.m16n8k16.row.col.f32.bf16.bf16.f32 "
        "{%0,%1,%2,%3}, {%4,%5,%6,%7}, {%8,%9}, {%0,%1,%2,%3};"
        : "+f"(c[0]), "+f"(c[1]), "+f"(c[2]), "+f"(c[3])
        : "r"(a0), "r"(a1), "r"(a2), "r"(a3), "r"(b0), "r"(b1));
}
__device__ __forceinline__ uint32_t lds_u32(uint32_t addr) {
    uint32_t v;
    asm volatile("ld.shared.b32 %0, [%1];" : "=r"(v) : "r"(addr));
    return v;
}
__device__ __forceinline__ float iou_f(float4 a, float4 b) {
    float areaA = (a.z - a.x) * (a.w - a.y);
    float areaB = (b.z - b.x) * (b.w - b.y);
    float lx = fmaxf(a.x, b.x), ly = fmaxf(a.y, b.y);
    float rx = fminf(a.z, b.z), ry = fminf(a.w, b.w);
    float w = fmaxf(rx - lx, 0.f), h = fmaxf(ry - ly, 0.f);
    float inter = w * h;
    return inter / (areaA + areaB - inter + 1e-9f);
}

// ---------------- GEMM: bf16 mma.sync, on-the-fly W conversion ----------------
__global__ __launch_bounds__(GTH, 3) void k_gemm(const float* __restrict__ x,
                                                 const float* __restrict__ Wc,
                                                 const float* __restrict__ Wd) {
    extern __shared__ char smem[];
    const uint32_t sb = smem_u32(smem);
    const int tid  = threadIdx.x;
    const int w    = tid >> 5;
    const int lane = tid & 31;
    const int g = lane >> 2;
    const int t = lane & 3;
    const int row0  = blockIdx.x * BMG;
    const int kbase = blockIdx.y * KPB;

    float acc[6][4];
#pragma unroll
    for (int nt = 0; nt < 6; nt++)
#pragma unroll
        for (int j = 0; j < 4; j++) acc[nt][j] = 0.f;

    float4 xr[8];
    float  wb[12];

    auto ldgA = [&](int ch) {
        const int k0 = kbase + ch * KC;
#pragma unroll
        for (int it = 0; it < 8; it++) {
            int q = tid + it * GTH;             // < 2048
            int r = q >> 4, quad = q & 15;
            xr[it] = *reinterpret_cast<const float4*>(
                &x[(size_t)(row0 + r) * D + k0 + quad * 4]);
        }
    };
    auto ldgB = [&](int ch) {
        const int k0 = kbase + ch * KC;
#pragma unroll
        for (int it = 0; it < 12; it++) {
            int q = tid + it * GTH;             // < 3072
            int kl = q / 48, nn = q % 48;
            float v = 0.f;
            if (nn < 21)      v = Wc[(size_t)(k0 + kl) * NC + nn];
            else if (nn < 42) v = Wd[(size_t)(k0 + kl) * NC + (nn - 21)];
            wb[it] = v;
        }
    };
    auto stsA = [&](int buf) {
        const uint32_t ab = sb + SM_A + buf * A_BYTES;
#pragma unroll
        for (int it = 0; it < 8; it++) {
            int q = tid + it * GTH;
            int r = q >> 4, quad = q & 15;
            uint2 v = make_uint2(pack_bf2(xr[it].x, xr[it].y),
                                 pack_bf2(xr[it].z, xr[it].w));
            asm volatile("st.shared.v2.b32 [%0], {%1, %2};"
                         :: "r"(ab + r * RS_A + quad * 8), "r"(v.x), "r"(v.y));
        }
    };
    auto stsB = [&](int buf) {
        const uint32_t bb = sb + SM_B + buf * B_BYTES;
#pragma unroll
        for (int it = 0; it < 12; it++) {
            int q = tid + it * GTH;
            int kl = q / 48, nn = q % 48;
            __nv_bfloat16 h = __float2bfloat16(wb[it]);
            unsigned short hs = *reinterpret_cast<unsigned short*>(&h);
            asm volatile("st.shared.b16 [%0], %1;"
                         :: "r"(bb + nn * RS_B + kl * 2), "h"(hs));
        }
    };

    ldgA(0); ldgB(0);
    const uint32_t a_base = sb + SM_A + (w * 16 + g) * RS_A + t * 4;
    const uint32_t b_base = sb + SM_B + g * RS_B + t * 4;

    for (int ch = 0; ch < NCH; ch++) {
        const int buf = ch & 1;
        stsA(buf); stsB(buf);
        __syncthreads();
        if (ch + 1 < NCH) { ldgA(ch + 1); ldgB(ch + 1); }
        const uint32_t ab = a_base + buf * A_BYTES;
        const uint32_t bb = b_base + buf * B_BYTES;
#pragma unroll
        for (int ks = 0; ks < 4; ks++) {
            const uint32_t ao = ab + ks * 32;
            uint32_t a0 = lds_u32(ao);
            uint32_t a1 = lds_u32(ao + 8 * RS_A);
            uint32_t a2 = lds_u32(ao + 16);
            uint32_t a3 = lds_u32(ao + 8 * RS_A + 16);
#pragma unroll
            for (int nt = 0; nt < 6; nt++) {
                uint32_t bo = bb + nt * 8 * RS_B + ks * 32;
                mma_bf16(acc[nt], a0, a1, a2, a3, lds_u32(bo), lds_u32(bo + 16));
            }
        }
        __syncthreads();
    }

    float* dst = &g_part[blockIdx.y][0];
    int row = row0 + w * 16 + g;
#pragma unroll
    for (int nt = 0; nt < 6; nt++) {
        int col = nt * 8 + 2 * t;
        *reinterpret_cast<float2*>(&dst[(size_t)row * NPAD + col]) =
            make_float2(acc[nt][0], acc[nt][1]);
        *reinterpret_cast<float2*>(&dst[(size_t)(row + 8) * NPAD + col]) =
            make_float2(acc[nt][2], acc[nt][3]);
    }
}

// ---------------- fused reduce: logits, exps, colparts, g_pre, bclip, resets ----------------
__global__ __launch_bounds__(256) void k_reduce(const float* __restrict__ b_cls,
                                                const float* __restrict__ b_det,
                                                const float* __restrict__ boxes) {
    __shared__ float scol[8][NC];
    const int tid  = threadIdx.x;
    const int wid  = tid >> 5;
    const int lane = tid & 31;
    if (tid < 8 * NC) scol[tid / NC][tid % NC] = 0.f;
    __syncthreads();
    const int row0 = blockIdx.x * 64;
    for (int q = tid; q < 64 * 2 * NC; q += 256) {
        int lr  = q / (2 * NC);
        int c   = q % (2 * NC);
        int row = row0 + lr;
        float s = 0.f;
#pragma unroll
        for (int ks = 0; ks < GKS; ks++) s += g_part[ks][(size_t)row * NPAD + c];
        if (c < NC) {
            g_cls[row * NC + c] = s + b_cls[c];
        } else {
            int cd = c - NC;
            float e = expf(s + b_det[cd]);
            if (cd < C) g_det[row * C + cd] = e;
            // 32 consecutive q -> distinct c within a warp (42 > 32): no RMW race
            scol[wid][cd] += e;
        }
    }
    for (int q = tid; q < 64 * C; q += 256) g_kept[row0 * C + q] = 0.f;
    if (tid < 64) {
        int row = row0 + tid;
        float4 b = reinterpret_cast<const float4*>(boxes)[row];
        g_bclip[row] = make_float4(fminf(fmaxf(b.x, 0.f), IMG_W),
                                   fminf(fmaxf(b.y, 0.f), IMG_H),
                                   fminf(fmaxf(b.z, 0.f), IMG_W),
                                   fminf(fmaxf(b.w, 0.f), IMG_H));
    }
    if (blockIdx.x == 0 && tid == 0) g_ncand = 0;
    __syncthreads();
    if (tid < NC) {
        float s = 0.f;
#pragma unroll
        for (int w2 = 0; w2 < 8; w2++) s += scol[w2][tid];
        g_colpart[blockIdx.x][tid] = s;
    }
    // phase 2: warp-per-row -> g_pre = cls_softmax * det_exp
#pragma unroll
    for (int rr = 0; rr < 8; rr++) {
        int row = row0 + rr * 8 + wid;
        float e = (lane < NC) ? expf(g_cls[row * NC + lane]) : 0.f;
        float s = e;
#pragma unroll
        for (int o = 16; o > 0; o >>= 1) s += __shfl_xor_sync(0xffffffffu, s, o);
        float inv = 1.f / s;
        if (lane < C) g_pre[row * C + lane] = e * inv * g_det[row * C + lane];
    }
}

// ---------------- per-class NMS + fused final top-k (last block) ----------------
__global__ __launch_bounds__(256) void k_nms_final(float* __restrict__ out) {
    __shared__ int scnt;
    __shared__ unsigned char ssupp[R];
    __shared__ float bv[256];
    __shared__ int   bfi[256];
    __shared__ int   bps[256];
    __shared__ int   s_base;
    __shared__ int   s_woff[8];
    __shared__ float s_cs;
    __shared__ bool  s_last;
    const int cls = blockIdx.x;
    const int tid = threadIdx.x;

    // this class's column softmax denominator (fixed-order, deterministic)
    if (tid < 32) {
        float s = g_colpart[tid][cls] + g_colpart[tid + 32][cls];
#pragma unroll
        for (int o = 16; o > 0; o >>= 1) s += __shfl_xor_sync(0xffffffffu, s, o);
        if (tid == 0) { s_cs = s; scnt = 0; }
    }
    __syncthreads();
    const float cs = s_cs;

    for (int r = tid; r < R; r += 256) {
        float v = g_pre[r * C + cls] / cs;
        if (v > SCORE_THRESH) {
            int p = atomicAdd(&scnt, 1);
            g_sidx[cls][p] = r;
            g_sval[cls][p] = v;
        }
    }
    __syncthreads();
    const int m = scnt;
    if (m > 0) {
        // rank sort: desc score, tie -> lower proposal index
        for (int i = tid; i < m; i += 256) {
            float vi = g_sval[cls][i];
            int   ri = g_sidx[cls][i];
            int rank = 0;
            for (int j = 0; j < m; j++) {
                float vj = g_sval[cls][j];
                int   rj = g_sidx[cls][j];
                if (vj > vi || (vj == vi && rj < ri)) rank++;
            }
            g_sorder[cls][rank] = i;
        }
        for (int q = tid; q < m; q += 256) ssupp[q] = 0;
        __syncthreads();
        for (int pos = 0; pos < m; pos++) {
            if (!ssupp[pos]) {
                int   i = g_sorder[cls][pos];
                int   r = g_sidx[cls][i];
                float v = g_sval[cls][i];
                if (tid == 0) {
                    g_kept[r * C + cls] = v;
                    int p = atomicAdd(&g_ncand, 1);
                    g_cand_val[p] = v;
                    g_cand_idx[p] = r * C + cls;
                }
                float4 bi = g_bclip[r];
                for (int q = pos + 1 + tid; q < m; q += 256) {
                    if (!ssupp[q]) {
                        int j = g_sorder[cls][q];
                        float4 bj = g_bclip[g_sidx[cls][j]];
                        if (iou_f(bi, bj) > NMS_THRESH) ssupp[q] = 1;
                    }
                }
            }
            __syncthreads();
        }
    }

    // completion counter: last class block runs the final top-k
    if (tid == 0) {
        __threadfence();
        s_last = (atomicAdd(&g_nmscnt, 1) == C - 1);
    }
    __syncthreads();
    if (!s_last) return;
    if (tid == 0) g_nmscnt = 0;
    __threadfence();

    int n = g_ncand;
    if (n > R * C) n = R * C;
    int take = n < TOPK ? n : TOPK;
    for (int round = 0; round < take; round++) {
        float best = -2.f; int bestfi = 0x7fffffff; int bestp = -1;
        for (int p = tid; p < n; p += 256) {
            float v = g_cand_val[p];
            if (v < 0.f) continue;
            int fi = g_cand_idx[p];
            if (v > best || (v == best && fi < bestfi)) {
                best = v; bestfi = fi; bestp = p;
            }
        }
        bv[tid] = best; bfi[tid] = bestfi; bps[tid] = bestp;
        __syncthreads();
        for (int s = 128; s > 0; s >>= 1) {
            if (tid < s) {
                if (bv[tid + s] > bv[tid] ||
                    (bv[tid + s] == bv[tid] && bfi[tid + s] < bfi[tid])) {
                    bv[tid] = bv[tid + s];
                    bfi[tid] = bfi[tid + s];
                    bps[tid] = bps[tid + s];
                }
            }
            __syncthreads();
        }
        if (tid == 0) {
            int fi = bfi[0];
            int prop = fi / C, cl = fi % C;
            float4 b = g_bclip[prop];
            out[round] = bv[0];
            out[TOPK + round * 4 + 0] = b.x;
            out[TOPK + round * 4 + 1] = b.y;
            out[TOPK + round * 4 + 2] = b.z;
            out[TOPK + round * 4 + 3] = b.w;
            out[TOPK + TOPK * 4 + round] = (float)cl;
            g_cand_val[bps[0]] = -1.f;
        }
        __syncthreads();
    }
    if (tid == 0) s_base = take;
    __syncthreads();
    for (int chunk = 0; chunk < R * C; chunk += 256) {
        if (s_base >= TOPK) break;
        int e = chunk + tid;
        bool f = (g_kept[e] == 0.f);
        unsigned bal = __ballot_sync(0xffffffffu, f);
        if ((tid & 31) == 0) s_woff[tid >> 5] = __popc(bal);
        __syncthreads();
        int pre = 0;
#pragma unroll
        for (int w2 = 0; w2 < 8; w2++)
            if (w2 < (tid >> 5)) pre += s_woff[w2];
        int rank = pre + __popc(bal & ((1u << (tid & 31)) - 1u));
        int slot = s_base + rank;
        if (f && slot < TOPK) {
            int prop = e / C, cl = e % C;
            float4 b = g_bclip[prop];
            out[slot] = 0.f;
            out[TOPK + slot * 4 + 0] = b.x;
            out[TOPK + slot * 4 + 1] = b.y;
            out[TOPK + slot * 4 + 2] = b.z;
            out[TOPK + slot * 4 + 3] = b.w;
            out[TOPK + TOPK * 4 + slot] = (float)cl;
        }
        __syncthreads();
        if (tid == 0) {
            int tot = 0;
#pragma unroll
            for (int w2 = 0; w2 < 8; w2++) tot += s_woff[w2];
            s_base += tot;
            if (s_base > TOPK) s_base = TOPK;
        }
        __syncthreads();
    }
}

extern "C" void kernel_launch(void* const* d_in, const int* in_sizes, int n_in,
                              void* d_out, int out_size) {
    const float* x     = (const float*)d_in[0];
    const float* boxes = (const float*)d_in[1];
    const float* W_cls = (const float*)d_in[2];
    const float* b_cls = (const float*)d_in[3];
    const float* W_det = (const float*)d_in[4];
    const float* b_det = (const float*)d_in[5];
    float* out = (float*)d_out;

    static bool attr_set = false;
    if (!attr_set) {
        cudaFuncSetAttribute(k_gemm, cudaFuncAttributeMaxDynamicSharedMemorySize,
                             SM_TOTAL);
        attr_set = true;
    }

    dim3 gg(GRB, GKS);
    k_gemm<<<gg, GTH, SM_TOTAL>>>(x, W_cls, W_det);
    k_reduce<<<64, 256>>>(b_cls, b_det, boxes);
    k_nms_final<<<C, 256>>>(out);
}

// round 8
// speedup vs baseline: 1.8726x; 1.8726x over previous
#include <cuda_runtime.h>
#include <cuda_bf16.h>
#include <math.h>
#include <stdint.h>

// ---------------- problem constants ----------------
constexpr int R    = 4096;
constexpr int D    = 4096;
constexpr int C    = 20;
constexpr int NC   = 21;
constexpr float IMG_W = 1216.0f;
constexpr float IMG_H = 800.0f;
constexpr float SCORE_THRESH = 0.05f;
constexpr float NMS_THRESH   = 0.5f;
constexpr int TOPK = 100;
constexpr int NPAD = 48;                 // 42 logit cols padded to 48

// ---------------- mma GEMM config ----------------
constexpr int BMG = 128;                 // M per CTA
constexpr int GRB = R / BMG;             // 32 row blocks
constexpr int GKS = 8;                   // K split
constexpr int KPB = D / GKS;             // 512 K per CTA
constexpr int KC  = 64;                  // K per chunk
constexpr int NCH = KPB / KC;            // 8 chunks
constexpr int GTH = 256;                 // 8 warps

// smem layout (bytes)
constexpr int RS_A    = 144;             // 64 bf16 = 128B + 16 pad (conflict-free lds)
constexpr int RS_B    = 144;
constexpr int A_BYTES = BMG * RS_A;      // 18432
constexpr int B_BYTES = NPAD * RS_B;     // 6912
constexpr int SM_A    = 0;
constexpr int SM_B    = 2 * A_BYTES;     // 36864
constexpr int SM_TOTAL = SM_B + 2 * B_BYTES;   // 50688

// ---------------- device scratch ----------------
__device__ __nv_bfloat16 g_WbfT[NPAD * D];   // W transposed+padded bf16, [n][k]
__device__ float g_part[GKS][R * NPAD];
__device__ float g_cls[R * NC];
__device__ float g_det[R * C];           // exp(det logit)
__device__ float g_pre[R * C];           // cls_softmax * det_exp (colsum pending)
__device__ float g_colpart[64][NC];
__device__ float4 g_bclip[R];
__device__ float g_kept[R * C];
__device__ int   g_ncand;
__device__ int   g_nmscnt;
__device__ float g_cand_val[R * C];
__device__ int   g_cand_idx[R * C];
__device__ int   g_sidx[C][R];
__device__ float g_sval[C][R];
__device__ int   g_sorder[C][R];

// ---------------- helpers ----------------
__device__ __forceinline__ uint32_t pack_bf2(float lo, float hi) {
    __nv_bfloat162 h = __floats2bfloat162_rn(lo, hi);
    return *reinterpret_cast<uint32_t*>(&h);
}
__device__ __forceinline__ uint32_t smem_u32(const void* p) {
    uint32_t a;
    asm("{ .reg .u64 t; cvta.to.shared.u64 t, %1; cvt.u32.u64 %0, t; }" : "=r"(a) : "l"(p));
    return a;
}
#define CP16(dst, src) \
    asm volatile("cp.async.ca.shared.global [%0], [%1], 16;" :: "r"(dst), "l"(src))
#define CP_COMMIT() asm volatile("cp.async.commit_group;" ::: "memory")
#define CP_WAIT0()  asm volatile("cp.async.wait_group 0;" ::: "memory")

__device__ __forceinline__ void mma_bf16(float* c, uint32_t a0, uint32_t a1,
                                         uint32_t a2, uint32_t a3,
                                         uint32_t b0, uint32_t b1) {
    asm volatile(
        "mma.sync.aligned.m16n8k16.row.col.f32.bf16.bf16.f32 "
        "{%0,%1,%2,%3}, {%4,%5,%6,%7}, {%8,%9}, {%0,%1,%2,%3};"
        : "+f"(c[0]), "+f"(c[1]), "+f"(c[2]), "+f"(c[3])
        : "r"(a0), "r"(a1), "r"(a2), "r"(a3), "r"(b0), "r"(b1));
}
__device__ __forceinline__ uint32_t lds_u32(uint32_t addr) {
    uint32_t v;
    asm volatile("ld.shared.b32 %0, [%1];" : "=r"(v) : "r"(addr));
    return v;
}
__device__ __forceinline__ float iou_f(float4 a, float4 b) {
    float areaA = (a.z - a.x) * (a.w - a.y);
    float areaB = (b.z - b.x) * (b.w - b.y);
    float lx = fmaxf(a.x, b.x), ly = fmaxf(a.y, b.y);
    float rx = fminf(a.z, b.z), ry = fminf(a.w, b.w);
    float w = fmaxf(rx - lx, 0.f), h = fmaxf(ry - ly, 0.f);
    float inter = w * h;
    return inter / (areaA + areaB - inter + 1e-9f);
}

// ---------------- W -> transposed bf16 [48][4096] ----------------
__global__ __launch_bounds__(256) void k_prep(const float* __restrict__ Wc,
                                              const float* __restrict__ Wd) {
    int idx = blockIdx.x * 256 + threadIdx.x;   // n * 2048 + kw
    if (idx >= NPAD * (D / 2)) return;
    int n  = idx >> 11;
    int kw = idx & 2047;
    float f0 = 0.f, f1 = 0.f;
    if (n < 21) {
        f0 = Wc[(size_t)(2 * kw) * NC + n];
        f1 = Wc[(size_t)(2 * kw + 1) * NC + n];
    } else if (n < 42) {
        f0 = Wd[(size_t)(2 * kw) * NC + (n - 21)];
        f1 = Wd[(size_t)(2 * kw + 1) * NC + (n - 21)];
    }
    reinterpret_cast<uint32_t*>(g_WbfT)[idx] = pack_bf2(f0, f1);
}

// ---------------- GEMM: bf16 mma.sync, A dbl-buffer LDG/STS, B dbl-buffer cp.async ----------------
__global__ __launch_bounds__(GTH, 3) void k_gemm(const float* __restrict__ x) {
    extern __shared__ char smem[];
    const uint32_t sb = smem_u32(smem);
    const int tid  = threadIdx.x;
    const int w    = tid >> 5;
    const int lane = tid & 31;
    const int g = lane >> 2;
    const int t = lane & 3;
    const int row0  = blockIdx.x * BMG;
    const int kbase = blockIdx.y * KPB;

    float acc[6][4];
#pragma unroll
    for (int nt = 0; nt < 6; nt++)
#pragma unroll
        for (int j = 0; j < 4; j++) acc[nt][j] = 0.f;

    float4 xr[8];

    auto ldgA = [&](int ch) {
        const int k0 = kbase + ch * KC;
#pragma unroll
        for (int it = 0; it < 8; it++) {
            int q = tid + it * GTH;             // < 2048
            int r = q >> 4, quad = q & 15;
            xr[it] = *reinterpret_cast<const float4*>(
                &x[(size_t)(row0 + r) * D + k0 + quad * 4]);
        }
    };
    auto stsA = [&](int buf) {
        const uint32_t ab = sb + SM_A + buf * A_BYTES;
#pragma unroll
        for (int it = 0; it < 8; it++) {
            int q = tid + it * GTH;
            int r = q >> 4, quad = q & 15;
            uint2 v = make_uint2(pack_bf2(xr[it].x, xr[it].y),
                                 pack_bf2(xr[it].z, xr[it].w));
            asm volatile("st.shared.v2.b32 [%0], {%1, %2};"
                         :: "r"(ab + r * RS_A + quad * 8), "r"(v.x), "r"(v.y));
        }
    };
    auto cpB = [&](int ch, int buf) {
        const uint32_t bb = sb + SM_B + buf * B_BYTES;
        const int k0 = kbase + ch * KC;
#pragma unroll
        for (int it = 0; it < 2; it++) {
            int q = tid + it * GTH;             // 384 total (48 n x 8 segs)
            if (q < 384) {
                int nn = q >> 3, seg = q & 7;
                CP16(bb + nn * RS_B + seg * 16,
                     reinterpret_cast<const char*>(g_WbfT) +
                         ((size_t)nn * D + k0) * 2 + seg * 16);
            }
        }
    };

    ldgA(0);
    cpB(0, 0); CP_COMMIT();

    const uint32_t a_base = sb + SM_A + (w * 16 + g) * RS_A + t * 4;
    const uint32_t b_base = sb + SM_B + g * RS_B + t * 4;

    for (int ch = 0; ch < NCH; ch++) {
        const int buf = ch & 1;
        stsA(buf);
        CP_WAIT0();                 // B chunk 'buf' resident
        __syncthreads();            // A stores + B visibility for all warps
        if (ch + 1 < NCH) {
            ldgA(ch + 1);           // register prefetch of next A chunk
            cpB(ch + 1, buf ^ 1);   // after barrier: nobody still reads B buf^1
            CP_COMMIT();
        }
        const uint32_t ab = a_base + buf * A_BYTES;
        const uint32_t bb = b_base + buf * B_BYTES;
#pragma unroll
        for (int ks = 0; ks < 4; ks++) {
            const uint32_t ao = ab + ks * 32;
            uint32_t a0 = lds_u32(ao);
            uint32_t a1 = lds_u32(ao + 8 * RS_A);
            uint32_t a2 = lds_u32(ao + 16);
            uint32_t a3 = lds_u32(ao + 8 * RS_A + 16);
#pragma unroll
            for (int nt = 0; nt < 6; nt++) {
                uint32_t bo = bb + nt * 8 * RS_B + ks * 32;
                mma_bf16(acc[nt], a0, a1, a2, a3, lds_u32(bo), lds_u32(bo + 16));
            }
        }
        __syncthreads();            // protect A buf from ch+2's stsA overwrite
    }

    float* dst = &g_part[blockIdx.y][0];
    int row = row0 + w * 16 + g;
#pragma unroll
    for (int nt = 0; nt < 6; nt++) {
        int col = nt * 8 + 2 * t;
        *reinterpret_cast<float2*>(&dst[(size_t)row * NPAD + col]) =
            make_float2(acc[nt][0], acc[nt][1]);
        *reinterpret_cast<float2*>(&dst[(size_t)(row + 8) * NPAD + col]) =
            make_float2(acc[nt][2], acc[nt][3]);
    }
}

// ---------------- fused reduce: logits, exps, colparts, g_pre, bclip, resets ----------------
__global__ __launch_bounds__(256) void k_reduce(const float* __restrict__ b_cls,
                                                const float* __restrict__ b_det,
                                                const float* __restrict__ boxes) {
    __shared__ float scol[8][NC];
    const int tid  = threadIdx.x;
    const int wid  = tid >> 5;
    const int lane = tid & 31;
    if (tid < 8 * NC) scol[tid / NC][tid % NC] = 0.f;
    __syncthreads();
    const int row0 = blockIdx.x * 64;
    for (int q = tid; q < 64 * 2 * NC; q += 256) {
        int lr  = q / (2 * NC);
        int c   = q % (2 * NC);
        int row = row0 + lr;
        float s = 0.f;
#pragma unroll
        for (int ks = 0; ks < GKS; ks++) s += g_part[ks][(size_t)row * NPAD + c];
        if (c < NC) {
            g_cls[row * NC + c] = s + b_cls[c];
        } else {
            int cd = c - NC;
            float e = expf(s + b_det[cd]);
            if (cd < C) g_det[row * C + cd] = e;
            // 32 consecutive q -> distinct c within a warp (42 > 32): no RMW race
            scol[wid][cd] += e;
        }
    }
    for (int q = tid; q < 64 * C; q += 256) g_kept[row0 * C + q] = 0.f;
    if (tid < 64) {
        int row = row0 + tid;
        float4 b = reinterpret_cast<const float4*>(boxes)[row];
        g_bclip[row] = make_float4(fminf(fmaxf(b.x, 0.f), IMG_W),
                                   fminf(fmaxf(b.y, 0.f), IMG_H),
                                   fminf(fmaxf(b.z, 0.f), IMG_W),
                                   fminf(fmaxf(b.w, 0.f), IMG_H));
    }
    if (blockIdx.x == 0 && tid == 0) g_ncand = 0;
    __syncthreads();
    if (tid < NC) {
        float s = 0.f;
#pragma unroll
        for (int w2 = 0; w2 < 8; w2++) s += scol[w2][tid];
        g_colpart[blockIdx.x][tid] = s;
    }
    // phase 2: warp-per-row -> g_pre = cls_softmax * det_exp
#pragma unroll
    for (int rr = 0; rr < 8; rr++) {
        int row = row0 + rr * 8 + wid;
        float e = (lane < NC) ? expf(g_cls[row * NC + lane]) : 0.f;
        float s = e;
#pragma unroll
        for (int o = 16; o > 0; o >>= 1) s += __shfl_xor_sync(0xffffffffu, s, o);
        float inv = 1.f / s;
        if (lane < C) g_pre[row * C + lane] = e * inv * g_det[row * C + lane];
    }
}

// ---------------- per-class NMS + fused final top-k (last block) ----------------
__global__ __launch_bounds__(256) void k_nms_final(float* __restrict__ out) {
    __shared__ int scnt;
    __shared__ unsigned char ssupp[R];
    __shared__ float bv[256];
    __shared__ int   bfi[256];
    __shared__ int   bps[256];
    __shared__ int   s_base;
    __shared__ int   s_woff[8];
    __shared__ float s_cs;
    __shared__ bool  s_last;
    const int cls = blockIdx.x;
    const int tid = threadIdx.x;

    // this class's column softmax denominator (fixed-order, deterministic)
    if (tid < 32) {
        float s = g_colpart[tid][cls] + g_colpart[tid + 32][cls];
#pragma unroll
        for (int o = 16; o > 0; o >>= 1) s += __shfl_xor_sync(0xffffffffu, s, o);
        if (tid == 0) { s_cs = s; scnt = 0; }
    }
    __syncthreads();
    const float cs = s_cs;

    for (int r = tid; r < R; r += 256) {
        float v = g_pre[r * C + cls] / cs;
        if (v > SCORE_THRESH) {
            int p = atomicAdd(&scnt, 1);
            g_sidx[cls][p] = r;
            g_sval[cls][p] = v;
        }
    }
    __syncthreads();
    const int m = scnt;
    if (m > 0) {
        // rank sort: desc score, tie -> lower proposal index
        for (int i = tid; i < m; i += 256) {
            float vi = g_sval[cls][i];
            int   ri = g_sidx[cls][i];
            int rank = 0;
            for (int j = 0; j < m; j++) {
                float vj = g_sval[cls][j];
                int   rj = g_sidx[cls][j];
                if (vj > vi || (vj == vi && rj < ri)) rank++;
            }
            g_sorder[cls][rank] = i;
        }
        for (int q = tid; q < m; q += 256) ssupp[q] = 0;
        __syncthreads();
        for (int pos = 0; pos < m; pos++) {
            if (!ssupp[pos]) {
                int   i = g_sorder[cls][pos];
                int   r = g_sidx[cls][i];
                float v = g_sval[cls][i];
                if (tid == 0) {
                    g_kept[r * C + cls] = v;
                    int p = atomicAdd(&g_ncand, 1);
                    g_cand_val[p] = v;
                    g_cand_idx[p] = r * C + cls;
                }
                float4 bi = g_bclip[r];
                for (int q = pos + 1 + tid; q < m; q += 256) {
                    if (!ssupp[q]) {
                        int j = g_sorder[cls][q];
                        float4 bj = g_bclip[g_sidx[cls][j]];
                        if (iou_f(bi, bj) > NMS_THRESH) ssupp[q] = 1;
                    }
                }
            }
            __syncthreads();
        }
    }

    // completion counter: last class block runs the final top-k
    if (tid == 0) {
        __threadfence();
        s_last = (atomicAdd(&g_nmscnt, 1) == C - 1);
    }
    __syncthreads();
    if (!s_last) return;
    if (tid == 0) g_nmscnt = 0;
    __threadfence();

    int n = g_ncand;
    if (n > R * C) n = R * C;
    int take = n < TOPK ? n : TOPK;
    for (int round = 0; round < take; round++) {
        float best = -2.f; int bestfi = 0x7fffffff; int bestp = -1;
        for (int p = tid; p < n; p += 256) {
            float v = g_cand_val[p];
            if (v < 0.f) continue;
            int fi = g_cand_idx[p];
            if (v > best || (v == best && fi < bestfi)) {
                best = v; bestfi = fi; bestp = p;
            }
        }
        bv[tid] = best; bfi[tid] = bestfi; bps[tid] = bestp;
        __syncthreads();
        for (int s = 128; s > 0; s >>= 1) {
            if (tid < s) {
                if (bv[tid + s] > bv[tid] ||
                    (bv[tid + s] == bv[tid] && bfi[tid + s] < bfi[tid])) {
                    bv[tid] = bv[tid + s];
                    bfi[tid] = bfi[tid + s];
                    bps[tid] = bps[tid + s];
                }
            }
            __syncthreads();
        }
        if (tid == 0) {
            int fi = bfi[0];
            int prop = fi / C, cl = fi % C;
            float4 b = g_bclip[prop];
            out[round] = bv[0];
            out[TOPK + round * 4 + 0] = b.x;
            out[TOPK + round * 4 + 1] = b.y;
            out[TOPK + round * 4 + 2] = b.z;
            out[TOPK + round * 4 + 3] = b.w;
            out[TOPK + TOPK * 4 + round] = (float)cl;
            g_cand_val[bps[0]] = -1.f;
        }
        __syncthreads();
    }
    if (tid == 0) s_base = take;
    __syncthreads();
    for (int chunk = 0; chunk < R * C; chunk += 256) {
        if (s_base >= TOPK) break;
        int e = chunk + tid;
        bool f = (g_kept[e] == 0.f);
        unsigned bal = __ballot_sync(0xffffffffu, f);
        if ((tid & 31) == 0) s_woff[tid >> 5] = __popc(bal);
        __syncthreads();
        int pre = 0;
#pragma unroll
        for (int w2 = 0; w2 < 8; w2++)
            if (w2 < (tid >> 5)) pre += s_woff[w2];
        int rank = pre + __popc(bal & ((1u << (tid & 31)) - 1u));
        int slot = s_base + rank;
        if (f && slot < TOPK) {
            int prop = e / C, cl = e % C;
            float4 b = g_bclip[prop];
            out[slot] = 0.f;
            out[TOPK + slot * 4 + 0] = b.x;
            out[TOPK + slot * 4 + 1] = b.y;
            out[TOPK + slot * 4 + 2] = b.z;
            out[TOPK + slot * 4 + 3] = b.w;
            out[TOPK + TOPK * 4 + slot] = (float)cl;
        }
        __syncthreads();
        if (tid == 0) {
            int tot = 0;
#pragma unroll
            for (int w2 = 0; w2 < 8; w2++) tot += s_woff[w2];
            s_base += tot;
            if (s_base > TOPK) s_base = TOPK;
        }
        __syncthreads();
    }
}

extern "C" void kernel_launch(void* const* d_in, const int* in_sizes, int n_in,
                              void* d_out, int out_size) {
    const float* x     = (const float*)d_in[0];
    const float* boxes = (const float*)d_in[1];
    const float* W_cls = (const float*)d_in[2];
    const float* b_cls = (const float*)d_in[3];
    const float* W_det = (const float*)d_in[4];
    const float* b_det = (const float*)d_in[5];
    float* out = (float*)d_out;

    static bool attr_set = false;
    if (!attr_set) {
        cudaFuncSetAttribute(k_gemm, cudaFuncAttributeMaxDynamicSharedMemorySize,
                             SM_TOTAL);
        attr_set = true;
    }

    k_prep<<<(NPAD * (D / 2) + 255) / 256, 256>>>(W_cls, W_det);
    dim3 gg(GRB, GKS);
    k_gemm<<<gg, GTH, SM_TOTAL>>>(x);
    k_reduce<<<64, 256>>>(b_cls, b_det, boxes);
    k_nms_final<<<C, 256>>>(out);
}

// round 9
// speedup vs baseline: 2.0978x; 1.1202x over previous
#include <cuda_runtime.h>
#include <cuda_bf16.h>
#include <math.h>
#include <stdint.h>

// ---------------- problem constants ----------------
constexpr int R    = 4096;
constexpr int D    = 4096;
constexpr int C    = 20;
constexpr int NC   = 21;
constexpr float IMG_W = 1216.0f;
constexpr float IMG_H = 800.0f;
constexpr float SCORE_THRESH = 0.05f;
constexpr float NMS_THRESH   = 0.5f;
constexpr int TOPK = 100;
constexpr int NPAD = 48;                 // 42 logit cols padded to 48

// ---------------- mma GEMM config ----------------
constexpr int BMG = 128;                 // M per CTA
constexpr int GRB = R / BMG;             // 32 row blocks
constexpr int GKS = 8;                   // K split
constexpr int KPB = D / GKS;             // 512 K per CTA
constexpr int KC  = 64;                  // K per chunk
constexpr int NCH = KPB / KC;            // 8 chunks
constexpr int GTH = 256;                 // 8 warps

// smem layout (bytes)
constexpr int RS_A    = 144;             // 64 bf16 = 128B + 16 pad
constexpr int RS_B    = 144;
constexpr int A_BYTES = BMG * RS_A;      // 18432
constexpr int B_BYTES = NPAD * RS_B;     // 6912
constexpr int SM_A    = 0;
constexpr int SM_B    = 2 * A_BYTES;     // 36864
constexpr int SM_TOTAL = SM_B + 2 * B_BYTES;   // 50688

// ---------------- device scratch ----------------
__device__ __nv_bfloat16 g_WbfT[NPAD * D];   // W transposed+padded bf16, [n][k]
__device__ float g_part[GKS][R * NPAD];
__device__ float g_preT[C * R];          // transposed: cls_softmax*det_exp, [cls][row]
__device__ float g_colpart[64][NC];
__device__ float4 g_bclip[R];
__device__ float g_kept[R * C];
__device__ int   g_ncand;
__device__ int   g_cnt1;                 // phase-1 completion counter
__device__ int   g_cnt2;                 // NMS completion counter
__device__ float g_cand_val[R * C];
__device__ int   g_cand_idx[R * C];
__device__ int   g_sidx[C][R];
__device__ float g_sval[C][R];
__device__ int   g_sorder[C][R];

// ---------------- helpers ----------------
__device__ __forceinline__ uint32_t pack_bf2(float lo, float hi) {
    __nv_bfloat162 h = __floats2bfloat162_rn(lo, hi);
    return *reinterpret_cast<uint32_t*>(&h);
}
__device__ __forceinline__ uint32_t smem_u32(const void* p) {
    uint32_t a;
    asm("{ .reg .u64 t; cvta.to.shared.u64 t, %1; cvt.u32.u64 %0, t; }" : "=r"(a) : "l"(p));
    return a;
}
#define CP16(dst, src) \
    asm volatile("cp.async.ca.shared.global [%0], [%1], 16;" :: "r"(dst), "l"(src))
#define CP_COMMIT() asm volatile("cp.async.commit_group;" ::: "memory")
#define CP_WAIT0()  asm volatile("cp.async.wait_group 0;" ::: "memory")

__device__ __forceinline__ void mma_bf16(float* c, uint32_t a0, uint32_t a1,
                                         uint32_t a2, uint32_t a3,
                                         uint32_t b0, uint32_t b1) {
    asm volatile(
        "mma.sync.aligned.m16n8k16.row.col.f32.bf16.bf16.f32 "
        "{%0,%1,%2,%3}, {%4,%5,%6,%7}, {%8,%9}, {%0,%1,%2,%3};"
        : "+f"(c[0]), "+f"(c[1]), "+f"(c[2]), "+f"(c[3])
        : "r"(a0), "r"(a1), "r"(a2), "r"(a3), "r"(b0), "r"(b1));
}
__device__ __forceinline__ uint32_t lds_u32(uint32_t addr) {
    uint32_t v;
    asm volatile("ld.shared.b32 %0, [%1];" : "=r"(v) : "r"(addr));
    return v;
}
__device__ __forceinline__ float iou_f(float4 a, float4 b) {
    float areaA = (a.z - a.x) * (a.w - a.y);
    float areaB = (b.z - b.x) * (b.w - b.y);
    float lx = fmaxf(a.x, b.x), ly = fmaxf(a.y, b.y);
    float rx = fminf(a.z, b.z), ry = fminf(a.w, b.w);
    float w = fmaxf(rx - lx, 0.f), h = fmaxf(ry - ly, 0.f);
    float inter = w * h;
    return inter / (areaA + areaB - inter + 1e-9f);
}

// ---------------- W -> transposed bf16 [48][4096] ----------------
__global__ __launch_bounds__(256) void k_prep(const float* __restrict__ Wc,
                                              const float* __restrict__ Wd) {
    int idx = blockIdx.x * 256 + threadIdx.x;   // n * 2048 + kw
    if (idx >= NPAD * (D / 2)) return;
    int n  = idx >> 11;
    int kw = idx & 2047;
    float f0 = 0.f, f1 = 0.f;
    if (n < 21) {
        f0 = Wc[(size_t)(2 * kw) * NC + n];
        f1 = Wc[(size_t)(2 * kw + 1) * NC + n];
    } else if (n < 42) {
        f0 = Wd[(size_t)(2 * kw) * NC + (n - 21)];
        f1 = Wd[(size_t)(2 * kw + 1) * NC + (n - 21)];
    }
    reinterpret_cast<uint32_t*>(g_WbfT)[idx] = pack_bf2(f0, f1);
}

// ---------------- GEMM: bf16 mma.sync (proven R8 structure) ----------------
__global__ __launch_bounds__(GTH, 3) void k_gemm(const float* __restrict__ x) {
    extern __shared__ char smem[];
    const uint32_t sb = smem_u32(smem);
    const int tid  = threadIdx.x;
    const int w    = tid >> 5;
    const int lane = tid & 31;
    const int g = lane >> 2;
    const int t = lane & 3;
    const int row0  = blockIdx.x * BMG;
    const int kbase = blockIdx.y * KPB;

    float acc[6][4];
#pragma unroll
    for (int nt = 0; nt < 6; nt++)
#pragma unroll
        for (int j = 0; j < 4; j++) acc[nt][j] = 0.f;

    float4 xr[8];

    auto ldgA = [&](int ch) {
        const int k0 = kbase + ch * KC;
#pragma unroll
        for (int it = 0; it < 8; it++) {
            int q = tid + it * GTH;
            int r = q >> 4, quad = q & 15;
            xr[it] = *reinterpret_cast<const float4*>(
                &x[(size_t)(row0 + r) * D + k0 + quad * 4]);
        }
    };
    auto stsA = [&](int buf) {
        const uint32_t ab = sb + SM_A + buf * A_BYTES;
#pragma unroll
        for (int it = 0; it < 8; it++) {
            int q = tid + it * GTH;
            int r = q >> 4, quad = q & 15;
            uint2 v = make_uint2(pack_bf2(xr[it].x, xr[it].y),
                                 pack_bf2(xr[it].z, xr[it].w));
            asm volatile("st.shared.v2.b32 [%0], {%1, %2};"
                         :: "r"(ab + r * RS_A + quad * 8), "r"(v.x), "r"(v.y));
        }
    };
    auto cpB = [&](int ch, int buf) {
        const uint32_t bb = sb + SM_B + buf * B_BYTES;
        const int k0 = kbase + ch * KC;
#pragma unroll
        for (int it = 0; it < 2; it++) {
            int q = tid + it * GTH;
            if (q < 384) {
                int nn = q >> 3, seg = q & 7;
                CP16(bb + nn * RS_B + seg * 16,
                     reinterpret_cast<const char*>(g_WbfT) +
                         ((size_t)nn * D + k0) * 2 + seg * 16);
            }
        }
    };

    ldgA(0);
    cpB(0, 0); CP_COMMIT();

    const uint32_t a_base = sb + SM_A + (w * 16 + g) * RS_A + t * 4;
    const uint32_t b_base = sb + SM_B + g * RS_B + t * 4;

    for (int ch = 0; ch < NCH; ch++) {
        const int buf = ch & 1;
        stsA(buf);
        CP_WAIT0();
        __syncthreads();
        if (ch + 1 < NCH) {
            ldgA(ch + 1);
            cpB(ch + 1, buf ^ 1);
            CP_COMMIT();
        }
        const uint32_t ab = a_base + buf * A_BYTES;
        const uint32_t bb = b_base + buf * B_BYTES;
#pragma unroll
        for (int ks = 0; ks < 4; ks++) {
            const uint32_t ao = ab + ks * 32;
            uint32_t a0 = lds_u32(ao);
            uint32_t a1 = lds_u32(ao + 8 * RS_A);
            uint32_t a2 = lds_u32(ao + 16);
            uint32_t a3 = lds_u32(ao + 8 * RS_A + 16);
#pragma unroll
            for (int nt = 0; nt < 6; nt++) {
                uint32_t bo = bb + nt * 8 * RS_B + ks * 32;
                mma_bf16(acc[nt], a0, a1, a2, a3, lds_u32(bo), lds_u32(bo + 16));
            }
        }
        __syncthreads();
    }

    float* dst = &g_part[blockIdx.y][0];
    int row = row0 + w * 16 + g;
#pragma unroll
    for (int nt = 0; nt < 6; nt++) {
        int col = nt * 8 + 2 * t;
        *reinterpret_cast<float2*>(&dst[(size_t)row * NPAD + col]) =
            make_float2(acc[nt][0], acc[nt][1]);
        *reinterpret_cast<float2*>(&dst[(size_t)(row + 8) * NPAD + col]) =
            make_float2(acc[nt][2], acc[nt][3]);
    }
}

// ---------------- fused tail: reduce + scores + NMS + topk, one launch ----------------
// grid = 64 blocks (all co-resident on 148 SMs -> spin is safe)
__global__ __launch_bounds__(256) void k_tail(const float* __restrict__ b_cls,
                                              const float* __restrict__ b_det,
                                              const float* __restrict__ boxes,
                                              float* __restrict__ out) {
    __shared__ float scol[8][NC];
    __shared__ float scls[64][NC];       // cls logits for this block's 64 rows
    __shared__ float sdet[64][C];        // det exps for this block's 64 rows
    __shared__ int   scnt;
    __shared__ unsigned char ssupp[R];
    __shared__ float bv[256];
    __shared__ int   bfi[256];
    __shared__ int   bps[256];
    __shared__ int   s_base;
    __shared__ int   s_woff[8];
    __shared__ float s_cs;
    __shared__ bool  s_last;

    const int tid  = threadIdx.x;
    const int wid  = tid >> 5;
    const int lane = tid & 31;
    const int row0 = blockIdx.x * 64;

    // ---- phase 1: reduce partials for rows [row0, row0+64) ----
    if (tid < 8 * NC) scol[tid / NC][tid % NC] = 0.f;
    __syncthreads();
    for (int q = tid; q < 64 * 2 * NC; q += 256) {
        int lr  = q / (2 * NC);
        int c   = q % (2 * NC);
        int row = row0 + lr;
        float s = 0.f;
#pragma unroll
        for (int ks = 0; ks < GKS; ks++) s += g_part[ks][(size_t)row * NPAD + c];
        if (c < NC) {
            scls[lr][c] = s + b_cls[c];
        } else {
            int cd = c - NC;
            float e = expf(s + b_det[cd]);
            if (cd < C) sdet[lr][cd] = e;
            // 32 consecutive q -> distinct c within a warp (42 > 32): no RMW race
            scol[wid][cd] += e;
        }
    }
    for (int q = tid; q < 64 * C; q += 256) g_kept[row0 * C + q] = 0.f;
    if (tid < 64) {
        int row = row0 + tid;
        float4 b = reinterpret_cast<const float4*>(boxes)[row];
        g_bclip[row] = make_float4(fminf(fmaxf(b.x, 0.f), IMG_W),
                                   fminf(fmaxf(b.y, 0.f), IMG_H),
                                   fminf(fmaxf(b.z, 0.f), IMG_W),
                                   fminf(fmaxf(b.w, 0.f), IMG_H));
    }
    if (blockIdx.x == 0 && tid == 0) g_ncand = 0;
    __syncthreads();
    if (tid < NC) {
        float s = 0.f;
#pragma unroll
        for (int w2 = 0; w2 < 8; w2++) s += scol[w2][tid];
        g_colpart[blockIdx.x][tid] = s;
    }
    // warp-per-row: g_preT[cls][row] = cls_softmax * det_exp
#pragma unroll
    for (int rr = 0; rr < 8; rr++) {
        int lr = rr * 8 + wid;
        float e = (lane < NC) ? expf(scls[lr][lane]) : 0.f;
        float s = e;
#pragma unroll
        for (int o = 16; o > 0; o >>= 1) s += __shfl_xor_sync(0xffffffffu, s, o);
        float inv = 1.f / s;
        if (lane < C) g_preT[lane * R + row0 + lr] = e * inv * sdet[lr][lane];
    }
    __syncthreads();

    // ---- barrier 1: all 64 blocks done with phase 1 ----
    if (tid == 0) {
        __threadfence();
        atomicAdd(&g_cnt1, 1);
    }
    if (blockIdx.x >= C) return;         // blocks 20..63 done
    if (tid == 0) {
        while (atomicAdd(&g_cnt1, 0) < 64) {}
    }
    __syncthreads();
    __threadfence();                     // acquire: other blocks' writes visible

    // ---- phase 2: per-class NMS (block = class), coalesced gather ----
    const int cls = blockIdx.x;
    if (tid < 32) {
        float s = g_colpart[tid][cls] + g_colpart[tid + 32][cls];
#pragma unroll
        for (int o = 16; o > 0; o >>= 1) s += __shfl_xor_sync(0xffffffffu, s, o);
        if (tid == 0) { s_cs = 1.f / s; scnt = 0; }
    }
    __syncthreads();
    const float ics = s_cs;

    for (int r = tid; r < R; r += 256) {
        float v = g_preT[cls * R + r] * ics;
        if (v > SCORE_THRESH) {
            int p = atomicAdd(&scnt, 1);
            g_sidx[cls][p] = r;
            g_sval[cls][p] = v;
        }
    }
    __syncthreads();
    const int m = scnt;
    if (m > 0) {
        // rank sort: desc score, tie -> lower proposal index
        for (int i = tid; i < m; i += 256) {
            float vi = g_sval[cls][i];
            int   ri = g_sidx[cls][i];
            int rank = 0;
            for (int j = 0; j < m; j++) {
                float vj = g_sval[cls][j];
                int   rj = g_sidx[cls][j];
                if (vj > vi || (vj == vi && rj < ri)) rank++;
            }
            g_sorder[cls][rank] = i;
        }
        for (int q = tid; q < m; q += 256) ssupp[q] = 0;
        __syncthreads();
        for (int pos = 0; pos < m; pos++) {
            if (!ssupp[pos]) {
                int   i = g_sorder[cls][pos];
                int   r = g_sidx[cls][i];
                float v = g_sval[cls][i];
                if (tid == 0) {
                    g_kept[r * C + cls] = v;
                    int p = atomicAdd(&g_ncand, 1);
                    g_cand_val[p] = v;
                    g_cand_idx[p] = r * C + cls;
                }
                float4 bi = g_bclip[r];
                for (int q = pos + 1 + tid; q < m; q += 256) {
                    if (!ssupp[q]) {
                        int j = g_sorder[cls][q];
                        float4 bj = g_bclip[g_sidx[cls][j]];
                        if (iou_f(bi, bj) > NMS_THRESH) ssupp[q] = 1;
                    }
                }
            }
            __syncthreads();
        }
    }

    // ---- barrier 2: last class block runs the final top-k ----
    if (tid == 0) {
        __threadfence();
        s_last = (atomicAdd(&g_cnt2, 1) == C - 1);
    }
    __syncthreads();
    if (!s_last) return;
    if (tid == 0) { g_cnt1 = 0; g_cnt2 = 0; }   // reset for next graph replay
    __threadfence();

    int n = g_ncand;
    if (n > R * C) n = R * C;
    int take = n < TOPK ? n : TOPK;
    for (int round = 0; round < take; round++) {
        float best = -2.f; int bestfi = 0x7fffffff; int bestp = -1;
        for (int p = tid; p < n; p += 256) {
            float v = g_cand_val[p];
            if (v < 0.f) continue;
            int fi = g_cand_idx[p];
            if (v > best || (v == best && fi < bestfi)) {
                best = v; bestfi = fi; bestp = p;
            }
        }
        bv[tid] = best; bfi[tid] = bestfi; bps[tid] = bestp;
        __syncthreads();
        for (int s = 128; s > 0; s >>= 1) {
            if (tid < s) {
                if (bv[tid + s] > bv[tid] ||
                    (bv[tid + s] == bv[tid] && bfi[tid + s] < bfi[tid])) {
                    bv[tid] = bv[tid + s];
                    bfi[tid] = bfi[tid + s];
                    bps[tid] = bps[tid + s];
                }
            }
            __syncthreads();
        }
        if (tid == 0) {
            int fi = bfi[0];
            int prop = fi / C, cl = fi % C;
            float4 b = g_bclip[prop];
            out[round] = bv[0];
            out[TOPK + round * 4 + 0] = b.x;
            out[TOPK + round * 4 + 1] = b.y;
            out[TOPK + round * 4 + 2] = b.z;
            out[TOPK + round * 4 + 3] = b.w;
            out[TOPK + TOPK * 4 + round] = (float)cl;
            g_cand_val[bps[0]] = -1.f;
        }
        __syncthreads();
    }
    if (tid == 0) s_base = take;
    __syncthreads();
    for (int chunk = 0; chunk < R * C; chunk += 256) {
        if (s_base >= TOPK) break;
        int e = chunk + tid;
        bool f = (g_kept[e] == 0.f);
        unsigned bal = __ballot_sync(0xffffffffu, f);
        if ((tid & 31) == 0) s_woff[tid >> 5] = __popc(bal);
        __syncthreads();
        int pre = 0;
#pragma unroll
        for (int w2 = 0; w2 < 8; w2++)
            if (w2 < (tid >> 5)) pre += s_woff[w2];
        int rank = pre + __popc(bal & ((1u << (tid & 31)) - 1u));
        int slot = s_base + rank;
        if (f && slot < TOPK) {
            int prop = e / C, cl = e % C;
            float4 b = g_bclip[prop];
            out[slot] = 0.f;
            out[TOPK + slot * 4 + 0] = b.x;
            out[TOPK + slot * 4 + 1] = b.y;
            out[TOPK + slot * 4 + 2] = b.z;
            out[TOPK + slot * 4 + 3] = b.w;
            out[TOPK + TOPK * 4 + slot] = (float)cl;
        }
        __syncthreads();
        if (tid == 0) {
            int tot = 0;
#pragma unroll
            for (int w2 = 0; w2 < 8; w2++) tot += s_woff[w2];
            s_base += tot;
            if (s_base > TOPK) s_base = TOPK;
        }
        __syncthreads();
    }
}

extern "C" void kernel_launch(void* const* d_in, const int* in_sizes, int n_in,
                              void* d_out, int out_size) {
    const float* x     = (const float*)d_in[0];
    const float* boxes = (const float*)d_in[1];
    const float* W_cls = (const float*)d_in[2];
    const float* b_cls = (const float*)d_in[3];
    const float* W_det = (const float*)d_in[4];
    const float* b_det = (const float*)d_in[5];
    float* out = (float*)d_out;

    static bool attr_set = false;
    if (!attr_set) {
        cudaFuncSetAttribute(k_gemm, cudaFuncAttributeMaxDynamicSharedMemorySize,
                             SM_TOTAL);
        attr_set = true;
    }

    k_prep<<<(NPAD * (D / 2) + 255) / 256, 256>>>(W_cls, W_det);
    dim3 gg(GRB, GKS);
    k_gemm<<<gg, GTH, SM_TOTAL>>>(x);
    k_tail<<<64, 256>>>(b_cls, b_det, boxes, out);
}

// round 10
// speedup vs baseline: 2.1014x; 1.0017x over previous
#include <cuda_runtime.h>
#include <cuda_bf16.h>
#include <math.h>
#include <stdint.h>

// ---------------- problem constants ----------------
constexpr int R    = 4096;
constexpr int D    = 4096;
constexpr int C    = 20;
constexpr int NC   = 21;
constexpr float IMG_W = 1216.0f;
constexpr float IMG_H = 800.0f;
constexpr float SCORE_THRESH = 0.05f;
constexpr float NMS_THRESH   = 0.5f;
constexpr int TOPK = 100;
constexpr int NPAD = 48;                 // 42 logit cols padded to 48

// ---------------- mma GEMM config ----------------
constexpr int BMG = 128;                 // M per CTA
constexpr int GRB = R / BMG;             // 32 row blocks
constexpr int GKS = 8;                   // K split
constexpr int KPB = D / GKS;             // 512 K per CTA
constexpr int KC  = 64;                  // K per chunk
constexpr int NCH = KPB / KC;            // 8 chunks
constexpr int GTH = 256;                 // 8 warps

// smem layout (bytes)
constexpr int RS_A    = 144;             // 64 bf16 = 128B + 16 pad
constexpr int RS_B    = 144;
constexpr int A_BYTES = BMG * RS_A;      // 18432
constexpr int B_BYTES = NPAD * RS_B;     // 6912
constexpr int SM_A    = 0;
constexpr int SM_B    = 2 * A_BYTES;     // 36864
constexpr int SM_TOTAL = SM_B + 2 * B_BYTES;   // 50688

// ---------------- device scratch ----------------
__device__ __nv_bfloat16 g_WbfT[NPAD * D];   // W transposed+padded bf16, [n][k]
__device__ float g_part[GKS][R * NPAD];
__device__ float g_preT[C * R];          // transposed: cls_softmax*det_exp, [cls][row]
__device__ float g_colpart[64][NC];
__device__ float4 g_bclip[R];
__device__ float g_kept[R * C];
__device__ int   g_ncand;
__device__ int   g_cnt1;
__device__ int   g_cnt2;
__device__ float g_cand_val[R * C];
__device__ int   g_cand_idx[R * C];
__device__ int   g_sidx[C][R];
__device__ float g_sval[C][R];
__device__ int   g_sorder[C][R];

// ---------------- helpers ----------------
__device__ __forceinline__ uint32_t pack_bf2(float lo, float hi) {
    __nv_bfloat162 h = __floats2bfloat162_rn(lo, hi);
    return *reinterpret_cast<uint32_t*>(&h);
}
__device__ __forceinline__ uint32_t smem_u32(const void* p) {
    uint32_t a;
    asm("{ .reg .u64 t; cvta.to.shared.u64 t, %1; cvt.u32.u64 %0, t; }" : "=r"(a) : "l"(p));
    return a;
}
#define CP16(dst, src) \
    asm volatile("cp.async.ca.shared.global [%0], [%1], 16;" :: "r"(dst), "l"(src))
#define CP_COMMIT() asm volatile("cp.async.commit_group;" ::: "memory")
#define CP_WAIT0()  asm volatile("cp.async.wait_group 0;" ::: "memory")

__device__ __forceinline__ void mma_bf16(float* c, uint32_t a0, uint32_t a1,
                                         uint32_t a2, uint32_t a3,
                                         uint32_t b0, uint32_t b1) {
    asm volatile(
        "mma.sync.aligned.m16n8k16.row.col.f32.bf16.bf16.f32 "
        "{%0,%1,%2,%3}, {%4,%5,%6,%7}, {%8,%9}, {%0,%1,%2,%3};"
        : "+f"(c[0]), "+f"(c[1]), "+f"(c[2]), "+f"(c[3])
        : "r"(a0), "r"(a1), "r"(a2), "r"(a3), "r"(b0), "r"(b1));
}
__device__ __forceinline__ void ldsm_x4(uint32_t& r0, uint32_t& r1,
                                        uint32_t& r2, uint32_t& r3, uint32_t addr) {
    asm volatile("ldmatrix.sync.aligned.m8n8.x4.shared.b16 {%0,%1,%2,%3}, [%4];"
                 : "=r"(r0), "=r"(r1), "=r"(r2), "=r"(r3) : "r"(addr));
}
__device__ __forceinline__ float iou_f(float4 a, float4 b) {
    float areaA = (a.z - a.x) * (a.w - a.y);
    float areaB = (b.z - b.x) * (b.w - b.y);
    float lx = fmaxf(a.x, b.x), ly = fmaxf(a.y, b.y);
    float rx = fminf(a.z, b.z), ry = fminf(a.w, b.w);
    float w = fmaxf(rx - lx, 0.f), h = fmaxf(ry - ly, 0.f);
    float inter = w * h;
    return inter / (areaA + areaB - inter + 1e-9f);
}

// ---------------- W -> transposed bf16 [48][4096], coalesced reads ----------------
__global__ __launch_bounds__(256) void k_prep(const float* __restrict__ Wc,
                                              const float* __restrict__ Wd) {
    int idx = blockIdx.x * 256 + threadIdx.x;
    if (idx < D * NC) {                          // 86016: one elem of each matrix
        int k = idx / NC;
        int n = idx - k * NC;
        g_WbfT[(size_t)n * D + k]        = __float2bfloat16(Wc[idx]);
        g_WbfT[(size_t)(NC + n) * D + k] = __float2bfloat16(Wd[idx]);
    } else {
        int q = idx - D * NC;                    // zero pad rows 42..47
        if (q < 6 * D) g_WbfT[(size_t)42 * D + q] = __float2bfloat16(0.f);
    }
}

// ---------------- GEMM: bf16 mma.sync + ldmatrix ----------------
__global__ __launch_bounds__(GTH, 3) void k_gemm(const float* __restrict__ x) {
    extern __shared__ char smem[];
    const uint32_t sb = smem_u32(smem);
    const int tid  = threadIdx.x;
    const int w    = tid >> 5;
    const int lane = tid & 31;
    const int g = lane >> 2;
    const int t = lane & 3;
    const int row0  = blockIdx.x * BMG;
    const int kbase = blockIdx.y * KPB;

    float acc[6][4];
#pragma unroll
    for (int nt = 0; nt < 6; nt++)
#pragma unroll
        for (int j = 0; j < 4; j++) acc[nt][j] = 0.f;

    float4 xr[8];

    auto ldgA = [&](int ch) {
        const int k0 = kbase + ch * KC;
#pragma unroll
        for (int it = 0; it < 8; it++) {
            int q = tid + it * GTH;
            int r = q >> 4, quad = q & 15;
            xr[it] = *reinterpret_cast<const float4*>(
                &x[(size_t)(row0 + r) * D + k0 + quad * 4]);
        }
    };
    auto stsA = [&](int buf) {
        const uint32_t ab = sb + SM_A + buf * A_BYTES;
#pragma unroll
        for (int it = 0; it < 8; it++) {
            int q = tid + it * GTH;
            int r = q >> 4, quad = q & 15;
            uint2 v = make_uint2(pack_bf2(xr[it].x, xr[it].y),
                                 pack_bf2(xr[it].z, xr[it].w));
            asm volatile("st.shared.v2.b32 [%0], {%1, %2};"
                         :: "r"(ab + r * RS_A + quad * 8), "r"(v.x), "r"(v.y));
        }
    };
    auto cpB = [&](int ch, int buf) {
        const uint32_t bb = sb + SM_B + buf * B_BYTES;
        const int k0 = kbase + ch * KC;
#pragma unroll
        for (int it = 0; it < 2; it++) {
            int q = tid + it * GTH;
            if (q < 384) {
                int nn = q >> 3, seg = q & 7;
                CP16(bb + nn * RS_B + seg * 16,
                     reinterpret_cast<const char*>(g_WbfT) +
                         ((size_t)nn * D + k0) * 2 + seg * 16);
            }
        }
    };

    ldgA(0);
    cpB(0, 0); CP_COMMIT();

    // ldmatrix lane address components
    const int part = lane >> 3;          // 0..3
    const int r8   = lane & 7;
    // A x4: sub0 rows0-7 kLo, sub1 rows8-15 kLo, sub2 rows0-7 kHi, sub3 rows8-15 kHi
    const uint32_t a_lm = sb + SM_A +
        (w * 16 + (part & 1) * 8 + r8) * RS_A + (part >> 1) * 16;
    // B x4 (pair p): sub0 n(0-7) kLo, sub1 n(0-7) kHi, sub2 n(8-15) kLo, sub3 n(8-15) kHi
    const uint32_t b_lm = sb + SM_B +
        ((part >> 1) * 8 + r8) * RS_B + (part & 1) * 16;

    for (int ch = 0; ch < NCH; ch++) {
        const int buf = ch & 1;
        stsA(buf);
        CP_WAIT0();
        __syncthreads();
        if (ch + 1 < NCH) {
            ldgA(ch + 1);
            cpB(ch + 1, buf ^ 1);
            CP_COMMIT();
        }
        const uint32_t ab = a_lm + buf * A_BYTES;
        const uint32_t bb = b_lm + buf * B_BYTES;
#pragma unroll
        for (int ks = 0; ks < 4; ks++) {
            uint32_t a0, a1, a2, a3;
            ldsm_x4(a0, a1, a2, a3, ab + ks * 32);
#pragma unroll
            for (int p = 0; p < 3; p++) {       // pairs of n-tiles
                uint32_t b0, b1, b2, b3;
                ldsm_x4(b0, b1, b2, b3, bb + p * 16 * RS_B + ks * 32);
                mma_bf16(acc[2 * p + 0], a0, a1, a2, a3, b0, b1);
                mma_bf16(acc[2 * p + 1], a0, a1, a2, a3, b2, b3);
            }
        }
        __syncthreads();
    }

    float* dst = &g_part[blockIdx.y][0];
    int row = row0 + w * 16 + g;
#pragma unroll
    for (int nt = 0; nt < 6; nt++) {
        int col = nt * 8 + 2 * t;
        *reinterpret_cast<float2*>(&dst[(size_t)row * NPAD + col]) =
            make_float2(acc[nt][0], acc[nt][1]);
        *reinterpret_cast<float2*>(&dst[(size_t)(row + 8) * NPAD + col]) =
            make_float2(acc[nt][2], acc[nt][3]);
    }
}

// ---------------- fused tail: reduce + scores + NMS + topk ----------------
__global__ __launch_bounds__(256) void k_tail(const float* __restrict__ b_cls,
                                              const float* __restrict__ b_det,
                                              const float* __restrict__ boxes,
                                              float* __restrict__ out) {
    __shared__ float scol[8][NC];
    __shared__ float scls[64][NC];
    __shared__ float sdet[64][C];
    __shared__ int   scnt;
    __shared__ unsigned char ssupp[R];
    __shared__ float bv[256];
    __shared__ int   bfi[256];
    __shared__ int   bps[256];
    __shared__ int   s_base;
    __shared__ int   s_woff[8];
    __shared__ float s_cs;
    __shared__ bool  s_last;

    const int tid  = threadIdx.x;
    const int wid  = tid >> 5;
    const int lane = tid & 31;
    const int row0 = blockIdx.x * 64;

    if (tid < 8 * NC) scol[tid / NC][tid % NC] = 0.f;
    __syncthreads();
    for (int q = tid; q < 64 * 2 * NC; q += 256) {
        int lr  = q / (2 * NC);
        int c   = q % (2 * NC);
        int row = row0 + lr;
        float s = 0.f;
#pragma unroll
        for (int ks = 0; ks < GKS; ks++) s += g_part[ks][(size_t)row * NPAD + c];
        if (c < NC) {
            scls[lr][c] = s + b_cls[c];
        } else {
            int cd = c - NC;
            float e = expf(s + b_det[cd]);
            if (cd < C) sdet[lr][cd] = e;
            scol[wid][cd] += e;   // 32 consecutive q -> distinct c (42 > 32)
        }
    }
    for (int q = tid; q < 64 * C; q += 256) g_kept[row0 * C + q] = 0.f;
    if (tid < 64) {
        int row = row0 + tid;
        float4 b = reinterpret_cast<const float4*>(boxes)[row];
        g_bclip[row] = make_float4(fminf(fmaxf(b.x, 0.f), IMG_W),
                                   fminf(fmaxf(b.y, 0.f), IMG_H),
                                   fminf(fmaxf(b.z, 0.f), IMG_W),
                                   fminf(fmaxf(b.w, 0.f), IMG_H));
    }
    if (blockIdx.x == 0 && tid == 0) g_ncand = 0;
    __syncthreads();
    if (tid < NC) {
        float s = 0.f;
#pragma unroll
        for (int w2 = 0; w2 < 8; w2++) s += scol[w2][tid];
        g_colpart[blockIdx.x][tid] = s;
    }
#pragma unroll
    for (int rr = 0; rr < 8; rr++) {
        int lr = rr * 8 + wid;
        float e = (lane < NC) ? expf(scls[lr][lane]) : 0.f;
        float s = e;
#pragma unroll
        for (int o = 16; o > 0; o >>= 1) s += __shfl_xor_sync(0xffffffffu, s, o);
        float inv = 1.f / s;
        if (lane < C) g_preT[lane * R + row0 + lr] = e * inv * sdet[lr][lane];
    }
    __syncthreads();

    if (tid == 0) {
        __threadfence();
        atomicAdd(&g_cnt1, 1);
    }
    if (blockIdx.x >= C) return;
    if (tid == 0) {
        while (atomicAdd(&g_cnt1, 0) < 64) {}
    }
    __syncthreads();
    __threadfence();

    const int cls = blockIdx.x;
    if (tid < 32) {
        float s = g_colpart[tid][cls] + g_colpart[tid + 32][cls];
#pragma unroll
        for (int o = 16; o > 0; o >>= 1) s += __shfl_xor_sync(0xffffffffu, s, o);
        if (tid == 0) { s_cs = 1.f / s; scnt = 0; }
    }
    __syncthreads();
    const float ics = s_cs;

    for (int r = tid; r < R; r += 256) {
        float v = g_preT[cls * R + r] * ics;
        if (v > SCORE_THRESH) {
            int p = atomicAdd(&scnt, 1);
            g_sidx[cls][p] = r;
            g_sval[cls][p] = v;
        }
    }
    __syncthreads();
    const int m = scnt;
    if (m > 0) {
        for (int i = tid; i < m; i += 256) {
            float vi = g_sval[cls][i];
            int   ri = g_sidx[cls][i];
            int rank = 0;
            for (int j = 0; j < m; j++) {
                float vj = g_sval[cls][j];
                int   rj = g_sidx[cls][j];
                if (vj > vi || (vj == vi && rj < ri)) rank++;
            }
            g_sorder[cls][rank] = i;
        }
        for (int q = tid; q < m; q += 256) ssupp[q] = 0;
        __syncthreads();
        for (int pos = 0; pos < m; pos++) {
            if (!ssupp[pos]) {
                int   i = g_sorder[cls][pos];
                int   r = g_sidx[cls][i];
                float v = g_sval[cls][i];
                if (tid == 0) {
                    g_kept[r * C + cls] = v;
                    int p = atomicAdd(&g_ncand, 1);
                    g_cand_val[p] = v;
                    g_cand_idx[p] = r * C + cls;
                }
                float4 bi = g_bclip[r];
                for (int q = pos + 1 + tid; q < m; q += 256) {
                    if (!ssupp[q]) {
                        int j = g_sorder[cls][q];
                        float4 bj = g_bclip[g_sidx[cls][j]];
                        if (iou_f(bi, bj) > NMS_THRESH) ssupp[q] = 1;
                    }
                }
            }
            __syncthreads();
        }
    }

    if (tid == 0) {
        __threadfence();
        s_last = (atomicAdd(&g_cnt2, 1) == C - 1);
    }
    __syncthreads();
    if (!s_last) return;
    if (tid == 0) { g_cnt1 = 0; g_cnt2 = 0; }
    __threadfence();

    int n = g_ncand;
    if (n > R * C) n = R * C;
    int take = n < TOPK ? n : TOPK;
    for (int round = 0; round < take; round++) {
        float best = -2.f; int bestfi = 0x7fffffff; int bestp = -1;
        for (int p = tid; p < n; p += 256) {
            float v = g_cand_val[p];
            if (v < 0.f) continue;
            int fi = g_cand_idx[p];
            if (v > best || (v == best && fi < bestfi)) {
                best = v; bestfi = fi; bestp = p;
            }
        }
        bv[tid] = best; bfi[tid] = bestfi; bps[tid] = bestp;
        __syncthreads();
        for (int s = 128; s > 0; s >>= 1) {
            if (tid < s) {
                if (bv[tid + s] > bv[tid] ||
                    (bv[tid + s] == bv[tid] && bfi[tid + s] < bfi[tid])) {
                    bv[tid] = bv[tid + s];
                    bfi[tid] = bfi[tid + s];
                    bps[tid] = bps[tid + s];
                }
            }
            __syncthreads();
        }
        if (tid == 0) {
            int fi = bfi[0];
            int prop = fi / C, cl = fi % C;
            float4 b = g_bclip[prop];
            out[round] = bv[0];
            out[TOPK + round * 4 + 0] = b.x;
            out[TOPK + round * 4 + 1] = b.y;
            out[TOPK + round * 4 + 2] = b.z;
            out[TOPK + round * 4 + 3] = b.w;
            out[TOPK + TOPK * 4 + round] = (float)cl;
            g_cand_val[bps[0]] = -1.f;
        }
        __syncthreads();
    }
    if (tid == 0) s_base = take;
    __syncthreads();
    for (int chunk = 0; chunk < R * C; chunk += 256) {
        if (s_base >= TOPK) break;
        int e = chunk + tid;
        bool f = (g_kept[e] == 0.f);
        unsigned bal = __ballot_sync(0xffffffffu, f);
        if ((tid & 31) == 0) s_woff[tid >> 5] = __popc(bal);
        __syncthreads();
        int pre = 0;
#pragma unroll
        for (int w2 = 0; w2 < 8; w2++)
            if (w2 < (tid >> 5)) pre += s_woff[w2];
        int rank = pre + __popc(bal & ((1u << (tid & 31)) - 1u));
        int slot = s_base + rank;
        if (f && slot < TOPK) {
            int prop = e / C, cl = e % C;
            float4 b = g_bclip[prop];
            out[slot] = 0.f;
            out[TOPK + slot * 4 + 0] = b.x;
            out[TOPK + slot * 4 + 1] = b.y;
            out[TOPK + slot * 4 + 2] = b.z;
            out[TOPK + slot * 4 + 3] = b.w;
            out[TOPK + TOPK * 4 + slot] = (float)cl;
        }
        __syncthreads();
        if (tid == 0) {
            int tot = 0;
#pragma unroll
            for (int w2 = 0; w2 < 8; w2++) tot += s_woff[w2];
            s_base += tot;
            if (s_base > TOPK) s_base = TOPK;
        }
        __syncthreads();
    }
}

extern "C" void kernel_launch(void* const* d_in, const int* in_sizes, int n_in,
                              void* d_out, int out_size) {
    const float* x     = (const float*)d_in[0];
    const float* boxes = (const float*)d_in[1];
    const float* W_cls = (const float*)d_in[2];
    const float* b_cls = (const float*)d_in[3];
    const float* W_det = (const float*)d_in[4];
    const float* b_det = (const float*)d_in[5];
    float* out = (float*)d_out;

    static bool attr_set = false;
    if (!attr_set) {
        cudaFuncSetAttribute(k_gemm, cudaFuncAttributeMaxDynamicSharedMemorySize,
                             SM_TOTAL);
        attr_set = true;
    }

    k_prep<<<(D * NC + 6 * D + 255) / 256, 256>>>(W_cls, W_det);
    dim3 gg(GRB, GKS);
    k_gemm<<<gg, GTH, SM_TOTAL>>>(x);
    k_tail<<<64, 256>>>(b_cls, b_det, boxes, out);
}

// round 11
// speedup vs baseline: 2.1808x; 1.0378x over previous
#include <cuda_runtime.h>
#include <cuda_bf16.h>
#include <math.h>
#include <stdint.h>

// ---------------- problem constants ----------------
constexpr int R    = 4096;
constexpr int D    = 4096;
constexpr int C    = 20;
constexpr int NC   = 21;
constexpr float IMG_W = 1216.0f;
constexpr float IMG_H = 800.0f;
constexpr float SCORE_THRESH = 0.05f;
constexpr float NMS_THRESH   = 0.5f;
constexpr int TOPK = 100;
constexpr int NPAD = 48;

// ---------------- mma GEMM config ----------------
constexpr int BMG = 128;
constexpr int GRB = R / BMG;             // 32 row blocks
constexpr int GKS = 8;                   // K split
constexpr int KPB = D / GKS;             // 512
constexpr int KC  = 64;
constexpr int NCH = KPB / KC;            // 8
constexpr int GTH = 256;
constexpr int NBLK = GRB * GKS;          // 256 total blocks

// smem layout (bytes)
constexpr int RS_A    = 144;
constexpr int RS_B    = 144;
constexpr int A_BYTES = BMG * RS_A;      // 18432
constexpr int B_BYTES = NPAD * RS_B;     // 6912
constexpr int SM_A    = 0;
constexpr int SM_B    = 2 * A_BYTES;     // 36864
constexpr int SM_TOTAL = SM_B + 2 * B_BYTES;   // 50688

// tail smem overlay (fits inside SM_TOTAL)
struct TailSmem {
    float scol[8][NC];
    float scls[64][NC];
    float sdet[64][C];
    float bv[256];
    int   bfi[256];
    int   bps[256];
    int   scnt;
    int   s_base;
    int   s_woff[8];
    float s_cs;
    int   s_last;
    unsigned char ssupp[R];
};
static_assert(sizeof(TailSmem) <= SM_TOTAL, "tail overlay too big");

// ---------------- device scratch ----------------
__device__ __nv_bfloat16 g_WbfT[NPAD * D];
__device__ float g_part[GKS][R * NPAD];
__device__ float g_preT[C * R];
__device__ float g_colpart[64][NC];
__device__ float4 g_bclip[R];
__device__ float g_kept[R * C];
__device__ int   g_ncand;
__device__ int   g_cnt1, g_cnt2, g_cnt3, g_cnt4;
__device__ float g_cand_val[R * C];
__device__ int   g_cand_idx[R * C];
__device__ int   g_sidx[C][R];
__device__ float g_sval[C][R];
__device__ int   g_sorder[C][R];

// ---------------- helpers ----------------
__device__ __forceinline__ uint32_t pack_bf2(float lo, float hi) {
    __nv_bfloat162 h = __floats2bfloat162_rn(lo, hi);
    return *reinterpret_cast<uint32_t*>(&h);
}
__device__ __forceinline__ uint32_t smem_u32(const void* p) {
    uint32_t a;
    asm("{ .reg .u64 t; cvta.to.shared.u64 t, %1; cvt.u32.u64 %0, t; }" : "=r"(a) : "l"(p));
    return a;
}
#define CP16(dst, src) \
    asm volatile("cp.async.ca.shared.global [%0], [%1], 16;" :: "r"(dst), "l"(src))
#define CP_COMMIT() asm volatile("cp.async.commit_group;" ::: "memory")
#define CP_WAIT0()  asm volatile("cp.async.wait_group 0;" ::: "memory")

__device__ __forceinline__ void mma_bf16(float* c, uint32_t a0, uint32_t a1,
                                         uint32_t a2, uint32_t a3,
                                         uint32_t b0, uint32_t b1) {
    asm volatile(
        "mma.sync.aligned.m16n8k16.row.col.f32.bf16.bf16.f32 "
        "{%0,%1,%2,%3}, {%4,%5,%6,%7}, {%8,%9}, {%0,%1,%2,%3};"
        : "+f"(c[0]), "+f"(c[1]), "+f"(c[2]), "+f"(c[3])
        : "r"(a0), "r"(a1), "r"(a2), "r"(a3), "r"(b0), "r"(b1));
}
__device__ __forceinline__ void ldsm_x4(uint32_t& r0, uint32_t& r1,
                                        uint32_t& r2, uint32_t& r3, uint32_t addr) {
    asm volatile("ldmatrix.sync.aligned.m8n8.x4.shared.b16 {%0,%1,%2,%3}, [%4];"
                 : "=r"(r0), "=r"(r1), "=r"(r2), "=r"(r3) : "r"(addr));
}
__device__ __forceinline__ float iou_f(float4 a, float4 b) {
    float areaA = (a.z - a.x) * (a.w - a.y);
    float areaB = (b.z - b.x) * (b.w - b.y);
    float lx = fmaxf(a.x, b.x), ly = fmaxf(a.y, b.y);
    float rx = fminf(a.z, b.z), ry = fminf(a.w, b.w);
    float w = fmaxf(rx - lx, 0.f), h = fmaxf(ry - ly, 0.f);
    float inter = w * h;
    return inter / (areaA + areaB - inter + 1e-9f);
}

// ---------------- ONE persistent kernel: prep + gemm + tail ----------------
__global__ __launch_bounds__(GTH, 2) void k_all(const float* __restrict__ x,
                                                const float* __restrict__ Wc,
                                                const float* __restrict__ Wd,
                                                const float* __restrict__ b_cls,
                                                const float* __restrict__ b_det,
                                                const float* __restrict__ boxes,
                                                float* __restrict__ out) {
    extern __shared__ char smem[];
    const uint32_t sb = smem_u32(smem);
    const int tid  = threadIdx.x;
    const int bid  = blockIdx.x;
    const int lane = tid & 31;
    const int w    = tid >> 5;
    const int g    = lane >> 2;
    const int t    = lane & 3;
    const int rb = bid & 31;             // row block
    const int ks = bid >> 5;             // K-split slice
    const int row0  = rb * BMG;
    const int kbase = ks * KPB;

    // ---- phase 0: cooperative W -> bf16 transposed (each block 16 k-rows) ----
    {
        const int b16 = bid * 16;
        if (tid < 16 * NC) {
            int kk = tid / NC, n = tid - (tid / NC) * NC;
            int k = b16 + kk;
            g_WbfT[(size_t)n * D + k]        = __float2bfloat16(Wc[(size_t)k * NC + n]);
            g_WbfT[(size_t)(NC + n) * D + k] = __float2bfloat16(Wd[(size_t)k * NC + n]);
        }
        if (tid < 48)   // zero pad rows 42..47 (6*4096 bf16 = 256 blocks * 48 u32)
            reinterpret_cast<uint32_t*>(g_WbfT)[(42 * D) / 2 + bid * 48 + tid] = 0u;
    }

    // ---- GEMM lambdas ----
    float acc[6][4];
#pragma unroll
    for (int nt = 0; nt < 6; nt++)
#pragma unroll
        for (int j = 0; j < 4; j++) acc[nt][j] = 0.f;
    float4 xr[8];

    auto ldgA = [&](int ch) {
        const int k0 = kbase + ch * KC;
#pragma unroll
        for (int it = 0; it < 8; it++) {
            int q = tid + it * GTH;
            int r = q >> 4, quad = q & 15;
            xr[it] = *reinterpret_cast<const float4*>(
                &x[(size_t)(row0 + r) * D + k0 + quad * 4]);
        }
    };
    auto stsA = [&](int buf) {
        const uint32_t ab = sb + SM_A + buf * A_BYTES;
#pragma unroll
        for (int it = 0; it < 8; it++) {
            int q = tid + it * GTH;
            int r = q >> 4, quad = q & 15;
            uint2 v = make_uint2(pack_bf2(xr[it].x, xr[it].y),
                                 pack_bf2(xr[it].z, xr[it].w));
            asm volatile("st.shared.v2.b32 [%0], {%1, %2};"
                         :: "r"(ab + r * RS_A + quad * 8), "r"(v.x), "r"(v.y));
        }
    };
    auto cpB = [&](int ch, int buf) {
        const uint32_t bb = sb + SM_B + buf * B_BYTES;
        const int k0 = kbase + ch * KC;
#pragma unroll
        for (int it = 0; it < 2; it++) {
            int q = tid + it * GTH;
            if (q < 384) {
                int nn = q >> 3, seg = q & 7;
                CP16(bb + nn * RS_B + seg * 16,
                     reinterpret_cast<const char*>(g_WbfT) +
                         ((size_t)nn * D + k0) * 2 + seg * 16);
            }
        }
    };

    ldgA(0);   // issue x prefetch before the barrier: spin hides LDG latency

    // ---- barrier 1: W conversion complete (all 256) ----
    if (tid == 0) {
        __threadfence();
        atomicAdd(&g_cnt1, 1);
        while (atomicAdd(&g_cnt1, 0) < NBLK) {}
    }
    __syncthreads();

    cpB(0, 0); CP_COMMIT();

    const int part = lane >> 3;
    const int r8   = lane & 7;
    const uint32_t a_lm = sb + SM_A +
        (w * 16 + (part & 1) * 8 + r8) * RS_A + (part >> 1) * 16;
    const uint32_t b_lm = sb + SM_B +
        ((part >> 1) * 8 + r8) * RS_B + (part & 1) * 16;

    for (int ch = 0; ch < NCH; ch++) {
        const int buf = ch & 1;
        stsA(buf);
        CP_WAIT0();
        __syncthreads();
        if (ch + 1 < NCH) {
            ldgA(ch + 1);
            cpB(ch + 1, buf ^ 1);
            CP_COMMIT();
        }
        const uint32_t ab = a_lm + buf * A_BYTES;
        const uint32_t bb = b_lm + buf * B_BYTES;
#pragma unroll
        for (int kq = 0; kq < 4; kq++) {
            uint32_t a0, a1, a2, a3;
            ldsm_x4(a0, a1, a2, a3, ab + kq * 32);
#pragma unroll
            for (int p = 0; p < 3; p++) {
                uint32_t b0, b1, b2, b3;
                ldsm_x4(b0, b1, b2, b3, bb + p * 16 * RS_B + kq * 32);
                mma_bf16(acc[2 * p + 0], a0, a1, a2, a3, b0, b1);
                mma_bf16(acc[2 * p + 1], a0, a1, a2, a3, b2, b3);
            }
        }
        __syncthreads();
    }

    {
        float* dst = &g_part[ks][0];
        int row = row0 + w * 16 + g;
#pragma unroll
        for (int nt = 0; nt < 6; nt++) {
            int col = nt * 8 + 2 * t;
            *reinterpret_cast<float2*>(&dst[(size_t)row * NPAD + col]) =
                make_float2(acc[nt][0], acc[nt][1]);
            *reinterpret_cast<float2*>(&dst[(size_t)(row + 8) * NPAD + col]) =
                make_float2(acc[nt][2], acc[nt][3]);
        }
    }

    // ---- barrier 2: all GEMM partials written ----
    if (tid == 0) {
        __threadfence();
        atomicAdd(&g_cnt2, 1);
    }
    if (bid >= 64) return;
    if (tid == 0) {
        while (atomicAdd(&g_cnt2, 0) < NBLK) {}
    }
    __syncthreads();
    __threadfence();

    // ---- tail phase 1 (blocks 0..63): reduce + softmax-pre + setup ----
    TailSmem* ts = reinterpret_cast<TailSmem*>(smem);
    const int row0t = bid * 64;

    if (tid < 8 * NC) ts->scol[tid / NC][tid % NC] = 0.f;
    __syncthreads();
    for (int q = tid; q < 64 * 2 * NC; q += 256) {
        int lr  = q / (2 * NC);
        int c   = q % (2 * NC);
        int row = row0t + lr;
        float s = 0.f;
#pragma unroll
        for (int k2 = 0; k2 < GKS; k2++) s += g_part[k2][(size_t)row * NPAD + c];
        if (c < NC) {
            ts->scls[lr][c] = s + b_cls[c];
        } else {
            int cd = c - NC;
            float e = expf(s + b_det[cd]);
            if (cd < C) ts->sdet[lr][cd] = e;
            ts->scol[w][cd] += e;   // 32 consecutive q -> distinct c (42 > 32)
        }
    }
    for (int q = tid; q < 64 * C; q += 256) g_kept[row0t * C + q] = 0.f;
    if (tid < 64) {
        int row = row0t + tid;
        float4 b = reinterpret_cast<const float4*>(boxes)[row];
        g_bclip[row] = make_float4(fminf(fmaxf(b.x, 0.f), IMG_W),
                                   fminf(fmaxf(b.y, 0.f), IMG_H),
                                   fminf(fmaxf(b.z, 0.f), IMG_W),
                                   fminf(fmaxf(b.w, 0.f), IMG_H));
    }
    if (bid == 0 && tid == 0) g_ncand = 0;
    __syncthreads();
    if (tid < NC) {
        float s = 0.f;
#pragma unroll
        for (int w2 = 0; w2 < 8; w2++) s += ts->scol[w2][tid];
        g_colpart[bid][tid] = s;
    }
#pragma unroll
    for (int rr = 0; rr < 8; rr++) {
        int lr = rr * 8 + w;
        float e = (lane < NC) ? expf(ts->scls[lr][lane]) : 0.f;
        float s = e;
#pragma unroll
        for (int o = 16; o > 0; o >>= 1) s += __shfl_xor_sync(0xffffffffu, s, o);
        float inv = 1.f / s;
        if (lane < C) g_preT[lane * R + row0t + lr] = e * inv * ts->sdet[lr][lane];
    }
    __syncthreads();

    // ---- barrier 3: phase 1 complete (64 blocks) ----
    if (tid == 0) {
        __threadfence();
        atomicAdd(&g_cnt3, 1);
    }
    if (bid >= C) return;
    if (tid == 0) {
        while (atomicAdd(&g_cnt3, 0) < 64) {}
    }
    __syncthreads();
    __threadfence();

    // ---- phase 2: per-class NMS (block = class) ----
    const int cls = bid;
    if (tid < 32) {
        float s = g_colpart[tid][cls] + g_colpart[tid + 32][cls];
#pragma unroll
        for (int o = 16; o > 0; o >>= 1) s += __shfl_xor_sync(0xffffffffu, s, o);
        if (tid == 0) { ts->s_cs = 1.f / s; ts->scnt = 0; }
    }
    __syncthreads();
    const float ics = ts->s_cs;

    for (int r = tid; r < R; r += 256) {
        float v = g_preT[cls * R + r] * ics;
        if (v > SCORE_THRESH) {
            int p = atomicAdd(&ts->scnt, 1);
            g_sidx[cls][p] = r;
            g_sval[cls][p] = v;
        }
    }
    __syncthreads();
    const int m = ts->scnt;
    if (m > 0) {
        for (int i = tid; i < m; i += 256) {
            float vi = g_sval[cls][i];
            int   ri = g_sidx[cls][i];
            int rank = 0;
            for (int j = 0; j < m; j++) {
                float vj = g_sval[cls][j];
                int   rj = g_sidx[cls][j];
                if (vj > vi || (vj == vi && rj < ri)) rank++;
            }
            g_sorder[cls][rank] = i;
        }
        for (int q = tid; q < m; q += 256) ts->ssupp[q] = 0;
        __syncthreads();
        for (int pos = 0; pos < m; pos++) {
            if (!ts->ssupp[pos]) {
                int   i = g_sorder[cls][pos];
                int   r = g_sidx[cls][i];
                float v = g_sval[cls][i];
                if (tid == 0) {
                    g_kept[r * C + cls] = v;
                    int p = atomicAdd(&g_ncand, 1);
                    g_cand_val[p] = v;
                    g_cand_idx[p] = r * C + cls;
                }
                float4 bi = g_bclip[r];
                for (int q = pos + 1 + tid; q < m; q += 256) {
                    if (!ts->ssupp[q]) {
                        int j = g_sorder[cls][q];
                        float4 bj = g_bclip[g_sidx[cls][j]];
                        if (iou_f(bi, bj) > NMS_THRESH) ts->ssupp[q] = 1;
                    }
                }
            }
            __syncthreads();
        }
    }

    // ---- barrier 4: last NMS block runs the final top-k ----
    if (tid == 0) {
        __threadfence();
        ts->s_last = (atomicAdd(&g_cnt4, 1) == C - 1) ? 1 : 0;
    }
    __syncthreads();
    if (!ts->s_last) return;
    if (tid == 0) { g_cnt1 = 0; g_cnt2 = 0; g_cnt3 = 0; g_cnt4 = 0; }
    __threadfence();

    int n = g_ncand;
    if (n > R * C) n = R * C;
    int take = n < TOPK ? n : TOPK;
    for (int round = 0; round < take; round++) {
        float best = -2.f; int bestfi = 0x7fffffff; int bestp = -1;
        for (int p = tid; p < n; p += 256) {
            float v = g_cand_val[p];
            if (v < 0.f) continue;
            int fi = g_cand_idx[p];
            if (v > best || (v == best && fi < bestfi)) {
                best = v; bestfi = fi; bestp = p;
            }
        }
        ts->bv[tid] = best; ts->bfi[tid] = bestfi; ts->bps[tid] = bestp;
        __syncthreads();
        for (int s = 128; s > 0; s >>= 1) {
            if (tid < s) {
                if (ts->bv[tid + s] > ts->bv[tid] ||
                    (ts->bv[tid + s] == ts->bv[tid] && ts->bfi[tid + s] < ts->bfi[tid])) {
                    ts->bv[tid] = ts->bv[tid + s];
                    ts->bfi[tid] = ts->bfi[tid + s];
                    ts->bps[tid] = ts->bps[tid + s];
                }
            }
            __syncthreads();
        }
        if (tid == 0) {
            int fi = ts->bfi[0];
            int prop = fi / C, cl = fi % C;
            float4 b = g_bclip[prop];
            out[round] = ts->bv[0];
            out[TOPK + round * 4 + 0] = b.x;
            out[TOPK + round * 4 + 1] = b.y;
            out[TOPK + round * 4 + 2] = b.z;
            out[TOPK + round * 4 + 3] = b.w;
            out[TOPK + TOPK * 4 + round] = (float)cl;
            g_cand_val[ts->bps[0]] = -1.f;
        }
        __syncthreads();
    }
    if (tid == 0) ts->s_base = take;
    __syncthreads();
    for (int chunk = 0; chunk < R * C; chunk += 256) {
        if (ts->s_base >= TOPK) break;
        int e = chunk + tid;
        bool f = (g_kept[e] == 0.f);
        unsigned bal = __ballot_sync(0xffffffffu, f);
        if ((tid & 31) == 0) ts->s_woff[tid >> 5] = __popc(bal);
        __syncthreads();
        int pre = 0;
#pragma unroll
        for (int w2 = 0; w2 < 8; w2++)
            if (w2 < (tid >> 5)) pre += ts->s_woff[w2];
        int rank = pre + __popc(bal & ((1u << (tid & 31)) - 1u));
        int slot = ts->s_base + rank;
        if (f && slot < TOPK) {
            int prop = e / C, cl = e % C;
            float4 b = g_bclip[prop];
            out[slot] = 0.f;
            out[TOPK + slot * 4 + 0] = b.x;
            out[TOPK + slot * 4 + 1] = b.y;
            out[TOPK + slot * 4 + 2] = b.z;
            out[TOPK + slot * 4 + 3] = b.w;
            out[TOPK + TOPK * 4 + slot] = (float)cl;
        }
        __syncthreads();
        if (tid == 0) {
            int tot = 0;
#pragma unroll
            for (int w2 = 0; w2 < 8; w2++) tot += ts->s_woff[w2];
            ts->s_base += tot;
            if (ts->s_base > TOPK) ts->s_base = TOPK;
        }
        __syncthreads();
    }
}

extern "C" void kernel_launch(void* const* d_in, const int* in_sizes, int n_in,
                              void* d_out, int out_size) {
    const float* x     = (const float*)d_in[0];
    const float* boxes = (const float*)d_in[1];
    const float* W_cls = (const float*)d_in[2];
    const float* b_cls = (const float*)d_in[3];
    const float* W_det = (const float*)d_in[4];
    const float* b_det = (const float*)d_in[5];
    float* out = (float*)d_out;

    static bool attr_set = false;
    if (!attr_set) {
        cudaFuncSetAttribute(k_all, cudaFuncAttributeMaxDynamicSharedMemorySize,
                             SM_TOTAL);
        attr_set = true;
    }

    k_all<<<NBLK, GTH, SM_TOTAL>>>(x, W_cls, W_det, b_cls, b_det, boxes, out);
}